// round 4
// baseline (speedup 1.0000x reference)
#include <cuda_runtime.h>
#include <math.h>

#define NN 100000
#define EE 1600000
#define SCAN_B 512
#define NB ((NN + SCAN_B - 1) / SCAN_B)

struct __align__(8) Edge { int s; float w; };

// ---------------- scratch (alloc-free: __device__ globals) ----------------
__device__ int   g_is64;
__device__ int   g_deg[NN];
__device__ int   g_cnt[NN];
__device__ int   g_off[NN];
__device__ int   g_cur[NN];
__device__ int   g_bsum[NB];
__device__ int   g_bpre[NB];
__device__ float g_dinv[NN];
__device__ float g_selfw[NN];
__device__ Edge  g_csr[EE];
__device__ float g_bufT[(size_t)NN * 128];
__device__ float g_bufO[(size_t)NN * 128];

// ---------------- packed f32x2 helpers ----------------
__device__ __forceinline__ void ffma2(double& acc, double w2, double x2) {
    asm("fma.rn.f32x2 %0, %1, %2, %0;" : "+d"(acc) : "d"(w2), "d"(x2));
}
__device__ __forceinline__ double dup2(float x) {
    double r; asm("mov.b64 %0, {%1, %1};" : "=d"(r) : "f"(x)); return r;
}
__device__ __forceinline__ float lo32(double d) { return __int_as_float(__double2loint(d)); }
__device__ __forceinline__ float hi32(double d) { return __int_as_float(__double2hiint(d)); }

// ---------------- detect dtype + init degrees ----------------
__global__ void k_pre0(const void* __restrict__ ei) {
    int i = blockIdx.x * blockDim.x + threadIdx.x;
    if (i < NN) g_deg[i] = 1;  // self-loop
    if (i == 0) {
        const int* w = (const int*)ei;
        int nz = 0;
        for (int k = 1; k < 256; k += 2) nz += (w[k] != 0);
        g_is64 = (nz == 0) ? 1 : 0;
    }
}

__device__ __forceinline__ int edge_at(const void* __restrict__ ei, long long i) {
    if (g_is64) return (int)((const long long*)ei)[i];
    return ((const int*)ei)[i];
}

__global__ void k_count_deg(const void* __restrict__ ei) {
    int i = blockIdx.x * blockDim.x + threadIdx.x;
    if (i < EE) atomicAdd(&g_deg[edge_at(ei, (long long)EE + i)], 1);
}

__global__ void k_dinv() {
    int i = blockIdx.x * blockDim.x + threadIdx.x;
    if (i < NN) {
        int dg = g_deg[i];
        float dv = rsqrtf((float)dg);
        g_dinv[i] = dv;
        g_selfw[i] = dv * dv;
        g_cnt[i] = dg - 1;
    }
}

// ---------------- CSR build: 2-level scan + scatter ----------------
__global__ void k_scan_local() {
    __shared__ int sm[SCAN_B];
    int v = blockIdx.x * SCAN_B + threadIdx.x;
    int x = (v < NN) ? g_cnt[v] : 0;
    sm[threadIdx.x] = x;
    __syncthreads();
    for (int off = 1; off < SCAN_B; off <<= 1) {
        int y = (threadIdx.x >= off) ? sm[threadIdx.x - off] : 0;
        __syncthreads();
        sm[threadIdx.x] += y;
        __syncthreads();
    }
    if (v < NN) g_off[v] = sm[threadIdx.x] - x;
    if (threadIdx.x == SCAN_B - 1) g_bsum[blockIdx.x] = sm[SCAN_B - 1];
}

__global__ void k_scan_bsum() {
    if (threadIdx.x == 0 && blockIdx.x == 0) {
        int run = 0;
        for (int i = 0; i < NB; i++) { g_bpre[i] = run; run += g_bsum[i]; }
    }
}

__global__ void k_scan_add() {
    int v = blockIdx.x * blockDim.x + threadIdx.x;
    if (v < NN) {
        g_off[v] += g_bpre[v / SCAN_B];
        g_cur[v] = 0;
    }
}

__global__ void k_build_csr(const void* __restrict__ ei) {
    int e = blockIdx.x * blockDim.x + threadIdx.x;
    if (e >= EE) return;
    int s = edge_at(ei, e);
    int d = edge_at(ei, (long long)EE + e);
    Edge ed;
    ed.s = s;
    ed.w = g_dinv[s] * g_dinv[d];
    int pos = g_off[d] + atomicAdd(&g_cur[d], 1);
    g_csr[pos] = ed;
}

// ---------------- dense transform with FFMA2: out[n,O] = X[n,K] @ W[K,O] ----
// Per thread: 4 rows x 8 cols. w pairs come pre-packed from smem (double2).
template <int K, int O>
__global__ void gemm_kernel(const float* __restrict__ X, const float* __restrict__ W,
                            float* __restrict__ out, int n) {
    constexpr int CG = O / 8;           // 8-col groups
    constexpr int RQ = 256 / CG;        // row-quads per block
    constexpr int ROWS = RQ * 4;
    extern __shared__ float sm[];
    float* Ws = sm;                     // K*O
    float* Xs = sm + K * O;             // ROWS*K
    int tid = threadIdx.x;
    int row0 = blockIdx.x * ROWS;

    for (int i = tid * 4; i < K * O; i += 256 * 4)
        *(float4*)&Ws[i] = *(const float4*)&W[i];
    for (int i = tid * 4; i < ROWS * K; i += 256 * 4) {
        int r = i / K, c = i % K;
        float4 v = make_float4(0.f, 0.f, 0.f, 0.f);
        if (row0 + r < n) v = *(const float4*)&X[(size_t)(row0 + r) * K + c];
        *(float4*)&Xs[i] = v;
    }
    __syncthreads();

    int cg = tid % CG, rq = tid / CG;
    int j = cg * 8;
    double acc[4][4];
#pragma unroll
    for (int i = 0; i < 4; i++)
#pragma unroll
        for (int p = 0; p < 4; p++) acc[i][p] = 0.0;

    const float* xb = &Xs[(rq * 4) * K];
#pragma unroll 4
    for (int k = 0; k < K; k++) {
        double2 wA = *(const double2*)&Ws[k * O + j];       // cols j..j+3
        double2 wB = *(const double2*)&Ws[k * O + j + 4];   // cols j+4..j+7
#pragma unroll
        for (int i = 0; i < 4; i++) {
            double xx = dup2(xb[i * K + k]);
            ffma2(acc[i][0], wA.x, xx);
            ffma2(acc[i][1], wA.y, xx);
            ffma2(acc[i][2], wB.x, xx);
            ffma2(acc[i][3], wB.y, xx);
        }
    }
#pragma unroll
    for (int i = 0; i < 4; i++) {
        int r = row0 + rq * 4 + i;
        if (r < n) {
            float4 o0 = make_float4(lo32(acc[i][0]), hi32(acc[i][0]),
                                    lo32(acc[i][1]), hi32(acc[i][1]));
            float4 o1 = make_float4(lo32(acc[i][2]), hi32(acc[i][2]),
                                    lo32(acc[i][3]), hi32(acc[i][3]));
            *(float4*)&out[(size_t)r * O + j] = o0;
            *(float4*)&out[(size_t)r * O + j + 4] = o1;
        }
    }
}

// ---------------- CSR gather + self-loop + bias + relu ----------------
template <int F>
__global__ void gather_kernel(const float* __restrict__ bias, float* __restrict__ O, int n) {
    constexpr int G = F / 4;
    int t = blockIdx.x * blockDim.x + threadIdx.x;
    int v = t / G;
    int q = t % G;
    if (v >= n) return;
    const float* T = g_bufT;

    float sw = g_selfw[v];
    float4 tv = *(const float4*)&T[(size_t)v * F + q * 4];
    float4 acc = make_float4(sw * tv.x, sw * tv.y, sw * tv.z, sw * tv.w);

    int beg = g_off[v];
    int cnt = g_cnt[v];
#pragma unroll 4
    for (int i = 0; i < cnt; i++) {
        Edge e = g_csr[beg + i];   // single LDG.64, warp-broadcast
        float4 x = *(const float4*)&T[(size_t)e.s * F + q * 4];
        acc.x += e.w * x.x; acc.y += e.w * x.y;
        acc.z += e.w * x.z; acc.w += e.w * x.w;
    }
    float4 b = *(const float4*)&bias[q * 4];
    acc.x = fmaxf(acc.x + b.x, 0.f);
    acc.y = fmaxf(acc.y + b.y, 0.f);
    acc.z = fmaxf(acc.z + b.z, 0.f);
    acc.w = fmaxf(acc.w + b.w, 0.f);
    *(float4*)&O[(size_t)v * F + q * 4] = acc;
}

// ---------------- layer-3 gather fused with logistic head ----------------
__global__ void gather_head_kernel(const float* __restrict__ bias,
                                   const float* __restrict__ Wl,
                                   const float* __restrict__ bl,
                                   float* __restrict__ out, int n) {
    constexpr int F = 32, G = 8;
    int t = blockIdx.x * blockDim.x + threadIdx.x;
    int v = t / G;
    int q = t % G;
    if (v >= n) return;
    const float* T = g_bufT;

    float sw = g_selfw[v];
    float4 tv = *(const float4*)&T[(size_t)v * F + q * 4];
    float4 acc = make_float4(sw * tv.x, sw * tv.y, sw * tv.z, sw * tv.w);

    int beg = g_off[v];
    int cnt = g_cnt[v];
#pragma unroll 4
    for (int i = 0; i < cnt; i++) {
        Edge e = g_csr[beg + i];
        float4 x = *(const float4*)&T[(size_t)e.s * F + q * 4];
        acc.x += e.w * x.x; acc.y += e.w * x.y;
        acc.z += e.w * x.z; acc.w += e.w * x.w;
    }
    float4 b = *(const float4*)&bias[q * 4];
    acc.x = fmaxf(acc.x + b.x, 0.f);
    acc.y = fmaxf(acc.y + b.y, 0.f);
    acc.z = fmaxf(acc.z + b.z, 0.f);
    acc.w = fmaxf(acc.w + b.w, 0.f);

    float4 w = *(const float4*)&Wl[q * 4];
    float p = acc.x * w.x + acc.y * w.y + acc.z * w.z + acc.w * w.w;
#pragma unroll
    for (int off = 4; off; off >>= 1) p += __shfl_down_sync(0xffffffffu, p, off, G);
    if (q == 0) out[v] = 1.f / (1.f + __expf(-(p + bl[0])));
}

extern "C" void kernel_launch(void* const* d_in, const int* in_sizes, int n_in,
                              void* d_out, int out_size) {
    const float* x = (const float*)d_in[0];
    const void* ei = (const void*)d_in[1];
    const float* W1 = (const float*)d_in[2];
    const float* b1 = (const float*)d_in[3];
    const float* W2 = (const float*)d_in[4];
    const float* b2 = (const float*)d_in[5];
    const float* W3 = (const float*)d_in[6];
    const float* b3 = (const float*)d_in[7];
    const float* Wl = (const float*)d_in[8];
    const float* bl = (const float*)d_in[9];
    float* out = (float*)d_out;
    int n = NN;

    cudaFuncSetAttribute(gemm_kernel<128, 128>, cudaFuncAttributeMaxDynamicSharedMemorySize, 98304);
    cudaFuncSetAttribute(gemm_kernel<128, 64>, cudaFuncAttributeMaxDynamicSharedMemorySize, 98304);
    cudaFuncSetAttribute(gemm_kernel<64, 32>, cudaFuncAttributeMaxDynamicSharedMemorySize, 73728);

    float* T;
    float* O;
    cudaGetSymbolAddress((void**)&T, g_bufT);
    cudaGetSymbolAddress((void**)&O, g_bufO);

    // preprocessing (gemm1 slotted at local launch #3 so ncu -s5 profiles it)
    k_pre0<<<(NN + 255) / 256, 256>>>(ei);
    k_count_deg<<<(EE + 255) / 256, 256>>>(ei);
    k_dinv<<<(NN + 255) / 256, 256>>>();

    // --- layer 1 GEMM: 128 -> 128 ---
    {
        constexpr int K = 128, Of = 128, ROWS = (256 / (Of / 8)) * 4;  // 64
        gemm_kernel<K, Of><<<(n + ROWS - 1) / ROWS, 256, (K * Of + ROWS * K) * 4>>>(x, W1, T, n);
    }

    // CSR build
    k_scan_local<<<NB, SCAN_B>>>();
    k_scan_bsum<<<1, 32>>>();
    k_scan_add<<<(NN + 255) / 256, 256>>>();
    k_build_csr<<<(EE + 255) / 256, 256>>>(ei);

    // --- layer 1 gather ---
    gather_kernel<128><<<(n * 32 + 255) / 256, 256>>>(b1, O, n);

    // --- layer 2: 128 -> 64 ---
    {
        constexpr int K = 128, Of = 64, ROWS = (256 / (Of / 8)) * 4;  // 128
        gemm_kernel<K, Of><<<(n + ROWS - 1) / ROWS, 256, (K * Of + ROWS * K) * 4>>>(O, W2, T, n);
        gather_kernel<Of><<<(n * (Of / 4) + 255) / 256, 256>>>(b2, O, n);
    }
    // --- layer 3: 64 -> 32 + head ---
    {
        constexpr int K = 64, Of = 32, ROWS = (256 / (Of / 8)) * 4;  // 256
        gemm_kernel<K, Of><<<(n + ROWS - 1) / ROWS, 256, (K * Of + ROWS * K) * 4>>>(O, W3, T, n);
        gather_head_kernel<<<(n * 8 + 255) / 256, 256>>>(b3, Wl, bl, out, n);
    }
}

// round 5
// speedup vs baseline: 1.2857x; 1.2857x over previous
#include <cuda_runtime.h>
#include <math.h>

#define NN 100000
#define EE 1600000
#define SCAN_B 512
#define NB ((NN + SCAN_B - 1) / SCAN_B)

struct __align__(8) Edge { int s; float w; };

// ---------------- scratch (alloc-free: __device__ globals) ----------------
__device__ int   g_is64;
__device__ int   g_deg[NN];
__device__ int   g_cnt[NN];
__device__ int   g_off[NN];
__device__ int   g_cur[NN];
__device__ int   g_bsum[NB];
__device__ int   g_bpre[NB];
__device__ float g_dinv[NN];
__device__ float g_selfw[NN];
__device__ Edge  g_csr[EE];
__device__ float g_bufT[(size_t)NN * 128];
__device__ float g_bufO[(size_t)NN * 128];

// ---------------- packed f32x2 helpers ----------------
__device__ __forceinline__ void ffma2(double& acc, double w2, double x2) {
    asm("fma.rn.f32x2 %0, %1, %2, %0;" : "+d"(acc) : "d"(w2), "d"(x2));
}
__device__ __forceinline__ double dup2(float x) {
    double r; asm("mov.b64 %0, {%1, %1};" : "=d"(r) : "f"(x)); return r;
}
__device__ __forceinline__ float lo32(double d) { return __int_as_float(__double2loint(d)); }
__device__ __forceinline__ float hi32(double d) { return __int_as_float(__double2hiint(d)); }

// ---------------- detect dtype + init degrees ----------------
__global__ void k_pre0(const void* __restrict__ ei) {
    int i = blockIdx.x * blockDim.x + threadIdx.x;
    if (i < NN) g_deg[i] = 1;  // self-loop
    if (i == 0) {
        const int* w = (const int*)ei;
        int nz = 0;
        for (int k = 1; k < 256; k += 2) nz += (w[k] != 0);
        g_is64 = (nz == 0) ? 1 : 0;
    }
}

__device__ __forceinline__ int edge_at(const void* __restrict__ ei, long long i) {
    if (g_is64) return (int)((const long long*)ei)[i];
    return ((const int*)ei)[i];
}

__global__ void k_count_deg(const void* __restrict__ ei) {
    int i = blockIdx.x * blockDim.x + threadIdx.x;
    if (i < EE) atomicAdd(&g_deg[edge_at(ei, (long long)EE + i)], 1);
}

__global__ void k_dinv() {
    int i = blockIdx.x * blockDim.x + threadIdx.x;
    if (i < NN) {
        int dg = g_deg[i];
        float dv = rsqrtf((float)dg);
        g_dinv[i] = dv;
        g_selfw[i] = dv * dv;
        g_cnt[i] = dg - 1;
    }
}

// ---------------- CSR build: 2-level scan + scatter ----------------
__global__ void k_scan_local() {
    __shared__ int sm[SCAN_B];
    int v = blockIdx.x * SCAN_B + threadIdx.x;
    int x = (v < NN) ? g_cnt[v] : 0;
    sm[threadIdx.x] = x;
    __syncthreads();
    for (int off = 1; off < SCAN_B; off <<= 1) {
        int y = (threadIdx.x >= off) ? sm[threadIdx.x - off] : 0;
        __syncthreads();
        sm[threadIdx.x] += y;
        __syncthreads();
    }
    if (v < NN) g_off[v] = sm[threadIdx.x] - x;
    if (threadIdx.x == SCAN_B - 1) g_bsum[blockIdx.x] = sm[SCAN_B - 1];
}

__global__ void k_scan_bsum() {
    if (threadIdx.x == 0 && blockIdx.x == 0) {
        int run = 0;
        for (int i = 0; i < NB; i++) { g_bpre[i] = run; run += g_bsum[i]; }
    }
}

__global__ void k_scan_add() {
    int v = blockIdx.x * blockDim.x + threadIdx.x;
    if (v < NN) {
        g_off[v] += g_bpre[v / SCAN_B];
        g_cur[v] = 0;
    }
}

__global__ void k_build_csr(const void* __restrict__ ei) {
    int e = blockIdx.x * blockDim.x + threadIdx.x;
    if (e >= EE) return;
    int s = edge_at(ei, e);
    int d = edge_at(ei, (long long)EE + e);
    Edge ed;
    ed.s = s;
    ed.w = g_dinv[s] * g_dinv[d];
    int pos = g_off[d] + atomicAdd(&g_cur[d], 1);
    g_csr[pos] = ed;
}

// ---------------- FFMA2 GEMM v2: out[n,O] = X[n,K] @ W[K,O] ----------------
// Warp covers all O cols (CPL cols/lane); 8 rows per lane; k blocked by 4.
// W per warp-k: one LDS per lane spanning O*4B (min crossbar phases).
// X per 4k: one broadcast float4 per row.
template <int K, int O, int CPL>
__global__ __launch_bounds__(256) void gemm2_kernel(const float* __restrict__ X,
                                                    const float* __restrict__ W,
                                                    float* __restrict__ out, int n) {
    constexpr int LPG = O / CPL;          // lanes spanning the O columns
    constexpr int RG = 32 / LPG;          // row-groups per warp
    constexpr int R = 8;                  // rows per lane
    constexpr int WARPS = 8;
    constexpr int ROWS = WARPS * RG * R;  // rows per block
    constexpr int NACC = CPL / 2;

    extern __shared__ float sm[];
    float* Ws = sm;                        // K*O
    float* Xs = sm + K * O;                // ROWS*K
    int tid = threadIdx.x;
    int row0 = blockIdx.x * ROWS;

    for (int i = tid * 4; i < K * O; i += 256 * 4)
        *(float4*)&Ws[i] = *(const float4*)&W[i];
    for (int i = tid * 4; i < ROWS * K; i += 256 * 4) {
        int r = i / K, c = i % K;
        float4 v = make_float4(0.f, 0.f, 0.f, 0.f);
        if (row0 + r < n) v = *(const float4*)&X[(size_t)(row0 + r) * K + c];
        *(float4*)&Xs[i] = v;
    }
    __syncthreads();

    int warp = tid >> 5, lane = tid & 31;
    int cg = lane % LPG, rg = lane / LPG;
    int j = cg * CPL;
    int rbase = (warp * RG + rg) * R;
    const float* xb = &Xs[rbase * K];

    double acc[R][NACC];
#pragma unroll
    for (int r = 0; r < R; r++)
#pragma unroll
        for (int p = 0; p < NACC; p++) acc[r][p] = 0.0;

#pragma unroll 2
    for (int k0 = 0; k0 < K; k0 += 4) {
        float4 xq[R];
#pragma unroll
        for (int r = 0; r < R; r++) xq[r] = *(const float4*)&xb[r * K + k0];
#pragma unroll
        for (int kk = 0; kk < 4; kk++) {
            const float* wrow = &Ws[(k0 + kk) * O + j];
            if constexpr (CPL == 4) {
                double2 w = *(const double2*)wrow;
#pragma unroll
                for (int r = 0; r < R; r++) {
                    float xv = (kk == 0) ? xq[r].x : (kk == 1) ? xq[r].y
                             : (kk == 2) ? xq[r].z : xq[r].w;
                    double xx = dup2(xv);
                    ffma2(acc[r][0], w.x, xx);
                    ffma2(acc[r][1], w.y, xx);
                }
            } else {
                double w = *(const double*)wrow;
#pragma unroll
                for (int r = 0; r < R; r++) {
                    float xv = (kk == 0) ? xq[r].x : (kk == 1) ? xq[r].y
                             : (kk == 2) ? xq[r].z : xq[r].w;
                    double xx = dup2(xv);
                    ffma2(acc[r][0], w, xx);
                }
            }
        }
    }

#pragma unroll
    for (int r = 0; r < R; r++) {
        int row = row0 + rbase + r;
        if (row < n) {
            if constexpr (CPL == 4) {
                float4 o = make_float4(lo32(acc[r][0]), hi32(acc[r][0]),
                                       lo32(acc[r][1]), hi32(acc[r][1]));
                *(float4*)&out[(size_t)row * O + j] = o;
            } else {
                float2 o = make_float2(lo32(acc[r][0]), hi32(acc[r][0]));
                *(float2*)&out[(size_t)row * O + j] = o;
            }
        }
    }
}

// ---------------- CSR gather + self-loop + bias + relu ----------------
template <int F>
__global__ void gather_kernel(const float* __restrict__ bias, float* __restrict__ O, int n) {
    constexpr int G = F / 4;
    int t = blockIdx.x * blockDim.x + threadIdx.x;
    int v = t / G;
    int q = t % G;
    if (v >= n) return;
    const float* T = g_bufT;

    float sw = g_selfw[v];
    float4 tv = *(const float4*)&T[(size_t)v * F + q * 4];
    float4 acc = make_float4(sw * tv.x, sw * tv.y, sw * tv.z, sw * tv.w);

    int beg = g_off[v];
    int cnt = g_cnt[v];
#pragma unroll 4
    for (int i = 0; i < cnt; i++) {
        Edge e = g_csr[beg + i];   // single LDG.64, warp-broadcast
        float4 x = *(const float4*)&T[(size_t)e.s * F + q * 4];
        acc.x += e.w * x.x; acc.y += e.w * x.y;
        acc.z += e.w * x.z; acc.w += e.w * x.w;
    }
    float4 b = *(const float4*)&bias[q * 4];
    acc.x = fmaxf(acc.x + b.x, 0.f);
    acc.y = fmaxf(acc.y + b.y, 0.f);
    acc.z = fmaxf(acc.z + b.z, 0.f);
    acc.w = fmaxf(acc.w + b.w, 0.f);
    *(float4*)&O[(size_t)v * F + q * 4] = acc;
}

// ---------------- layer-3 gather fused with logistic head ----------------
__global__ void gather_head_kernel(const float* __restrict__ bias,
                                   const float* __restrict__ Wl,
                                   const float* __restrict__ bl,
                                   float* __restrict__ out, int n) {
    constexpr int F = 32, G = 8;
    int t = blockIdx.x * blockDim.x + threadIdx.x;
    int v = t / G;
    int q = t % G;
    if (v >= n) return;
    const float* T = g_bufT;

    float sw = g_selfw[v];
    float4 tv = *(const float4*)&T[(size_t)v * F + q * 4];
    float4 acc = make_float4(sw * tv.x, sw * tv.y, sw * tv.z, sw * tv.w);

    int beg = g_off[v];
    int cnt = g_cnt[v];
#pragma unroll 4
    for (int i = 0; i < cnt; i++) {
        Edge e = g_csr[beg + i];
        float4 x = *(const float4*)&T[(size_t)e.s * F + q * 4];
        acc.x += e.w * x.x; acc.y += e.w * x.y;
        acc.z += e.w * x.z; acc.w += e.w * x.w;
    }
    float4 b = *(const float4*)&bias[q * 4];
    acc.x = fmaxf(acc.x + b.x, 0.f);
    acc.y = fmaxf(acc.y + b.y, 0.f);
    acc.z = fmaxf(acc.z + b.z, 0.f);
    acc.w = fmaxf(acc.w + b.w, 0.f);

    float4 w = *(const float4*)&Wl[q * 4];
    float p = acc.x * w.x + acc.y * w.y + acc.z * w.z + acc.w * w.w;
#pragma unroll
    for (int off = 4; off; off >>= 1) p += __shfl_down_sync(0xffffffffu, p, off, G);
    if (q == 0) out[v] = 1.f / (1.f + __expf(-(p + bl[0])));
}

extern "C" void kernel_launch(void* const* d_in, const int* in_sizes, int n_in,
                              void* d_out, int out_size) {
    const float* x = (const float*)d_in[0];
    const void* ei = (const void*)d_in[1];
    const float* W1 = (const float*)d_in[2];
    const float* b1 = (const float*)d_in[3];
    const float* W2 = (const float*)d_in[4];
    const float* b2 = (const float*)d_in[5];
    const float* W3 = (const float*)d_in[6];
    const float* b3 = (const float*)d_in[7];
    const float* Wl = (const float*)d_in[8];
    const float* bl = (const float*)d_in[9];
    float* out = (float*)d_out;
    int n = NN;

    cudaFuncSetAttribute(gemm2_kernel<128, 128, 4>, cudaFuncAttributeMaxDynamicSharedMemorySize, 98304);
    cudaFuncSetAttribute(gemm2_kernel<128, 64, 2>, cudaFuncAttributeMaxDynamicSharedMemorySize, 65536);
    cudaFuncSetAttribute(gemm2_kernel<64, 32, 2>, cudaFuncAttributeMaxDynamicSharedMemorySize, 40960);

    float* T;
    float* O;
    cudaGetSymbolAddress((void**)&T, g_bufT);
    cudaGetSymbolAddress((void**)&O, g_bufO);

    // preprocessing (gemm1 slotted so ncu profiles it, same order as round 4)
    k_pre0<<<(NN + 255) / 256, 256>>>(ei);
    k_count_deg<<<(EE + 255) / 256, 256>>>(ei);
    k_dinv<<<(NN + 255) / 256, 256>>>();

    // --- layer 1 GEMM: 128 -> 128 (64 rows/block) ---
    gemm2_kernel<128, 128, 4><<<(n + 63) / 64, 256, 98304>>>(x, W1, T, n);

    // CSR build
    k_scan_local<<<NB, SCAN_B>>>();
    k_scan_bsum<<<1, 32>>>();
    k_scan_add<<<(NN + 255) / 256, 256>>>();
    k_build_csr<<<(EE + 255) / 256, 256>>>(ei);

    // --- layer 1 gather ---
    gather_kernel<128><<<(n * 32 + 255) / 256, 256>>>(b1, O, n);

    // --- layer 2: 128 -> 64 (64 rows/block) ---
    gemm2_kernel<128, 64, 2><<<(n + 63) / 64, 256, 65536>>>(O, W2, T, n);
    gather_kernel<64><<<(n * 16 + 255) / 256, 256>>>(b2, O, n);

    // --- layer 3: 64 -> 32 (128 rows/block) + head ---
    gemm2_kernel<64, 32, 2><<<(n + 127) / 128, 256, 40960>>>(O, W3, T, n);
    gather_head_kernel<<<(n * 8 + 255) / 256, 256>>>(b3, Wl, bl, out, n);
}

// round 6
// speedup vs baseline: 1.3528x; 1.0522x over previous
#include <cuda_runtime.h>
#include <cuda_fp16.h>
#include <math.h>

#define NN 100000
#define EE 1600000
#define SCAN_B 512
#define NB ((NN + SCAN_B - 1) / SCAN_B)

struct __align__(8) Edge { int s; float w; };
struct __align__(8) Half4 { __half2 a, b; };

// ---------------- scratch (alloc-free: __device__ globals) ----------------
__device__ int    g_is64;
__device__ int    g_deg[NN];
__device__ int    g_cnt[NN];
__device__ int    g_off[NN];
__device__ int    g_cur[NN];
__device__ int    g_bsum[NB];
__device__ int    g_bpre[NB];
__device__ float  g_dinv[NN];
__device__ float  g_selfw[NN];
__device__ Edge   g_csr[EE];
__device__ __half g_bufT[(size_t)NN * 128];   // transformed features, fp16
__device__ float  g_bufO[(size_t)NN * 128];   // activations, fp32

// ---------------- packed f32x2 helpers ----------------
__device__ __forceinline__ void ffma2(double& acc, double w2, double x2) {
    asm("fma.rn.f32x2 %0, %1, %2, %0;" : "+d"(acc) : "d"(w2), "d"(x2));
}
__device__ __forceinline__ double dup2(float x) {
    double r; asm("mov.b64 %0, {%1, %1};" : "=d"(r) : "f"(x)); return r;
}
__device__ __forceinline__ float lo32(double d) { return __int_as_float(__double2loint(d)); }
__device__ __forceinline__ float hi32(double d) { return __int_as_float(__double2hiint(d)); }

// ---------------- detect dtype + init degrees ----------------
__global__ void k_pre0(const void* __restrict__ ei) {
    int i = blockIdx.x * blockDim.x + threadIdx.x;
    if (i < NN) g_deg[i] = 1;  // self-loop
    if (i == 0) {
        const int* w = (const int*)ei;
        int nz = 0;
        for (int k = 1; k < 256; k += 2) nz += (w[k] != 0);
        g_is64 = (nz == 0) ? 1 : 0;
    }
}

__device__ __forceinline__ int edge_at(const void* __restrict__ ei, long long i) {
    if (g_is64) return (int)((const long long*)ei)[i];
    return ((const int*)ei)[i];
}

__global__ void k_count_deg(const void* __restrict__ ei) {
    int i = blockIdx.x * blockDim.x + threadIdx.x;
    if (i < EE) atomicAdd(&g_deg[edge_at(ei, (long long)EE + i)], 1);
}

__global__ void k_dinv() {
    int i = blockIdx.x * blockDim.x + threadIdx.x;
    if (i < NN) {
        int dg = g_deg[i];
        float dv = rsqrtf((float)dg);
        g_dinv[i] = dv;
        g_selfw[i] = dv * dv;
        g_cnt[i] = dg - 1;
    }
}

// ---------------- CSR build ----------------
__global__ void k_scan_local() {
    __shared__ int sm[SCAN_B];
    int v = blockIdx.x * SCAN_B + threadIdx.x;
    int x = (v < NN) ? g_cnt[v] : 0;
    sm[threadIdx.x] = x;
    __syncthreads();
    for (int off = 1; off < SCAN_B; off <<= 1) {
        int y = (threadIdx.x >= off) ? sm[threadIdx.x - off] : 0;
        __syncthreads();
        sm[threadIdx.x] += y;
        __syncthreads();
    }
    if (v < NN) g_off[v] = sm[threadIdx.x] - x;
    if (threadIdx.x == SCAN_B - 1) g_bsum[blockIdx.x] = sm[SCAN_B - 1];
}

__global__ void k_scan_bsum() {
    if (threadIdx.x == 0 && blockIdx.x == 0) {
        int run = 0;
        for (int i = 0; i < NB; i++) { g_bpre[i] = run; run += g_bsum[i]; }
    }
}

__global__ void k_scan_add() {
    int v = blockIdx.x * blockDim.x + threadIdx.x;
    if (v < NN) {
        g_off[v] += g_bpre[v / SCAN_B];
        g_cur[v] = 0;
    }
}

__global__ void k_build_csr(const void* __restrict__ ei) {
    int e = blockIdx.x * blockDim.x + threadIdx.x;
    if (e >= EE) return;
    int s = edge_at(ei, e);
    int d = edge_at(ei, (long long)EE + e);
    Edge ed;
    ed.s = s;
    ed.w = g_dinv[s] * g_dinv[d];
    int pos = g_off[d] + atomicAdd(&g_cur[d], 1);
    g_csr[pos] = ed;
}

// ---------------- FFMA2 GEMM v3: half-precision store, O-sliced blocks ------
// Block covers OB columns (slice c0 = blockIdx.y*OB). CPL=4 cols/lane.
// LPG = OB/4 lanes per row-group; RG = 32/LPG; R = 4 rows/lane.
template <int K, int O, int OB>
__global__ __launch_bounds__(256) void gemm3_kernel(const float* __restrict__ X,
                                                    const float* __restrict__ W,
                                                    __half* __restrict__ out, int n) {
    constexpr int LPG = OB / 4;
    constexpr int RG = 32 / LPG;
    constexpr int R = 4;
    constexpr int ROWS = 8 * RG * R;
    extern __shared__ float sm[];
    float* Ws = sm;                 // K*OB
    float* Xs = sm + K * OB;        // ROWS*K
    int tid = threadIdx.x;
    int row0 = blockIdx.x * ROWS;
    int c0 = blockIdx.y * OB;

    for (int i = tid * 4; i < K * OB; i += 256 * 4) {
        int k = i / OB, c = i % OB;
        *(float4*)&Ws[i] = *(const float4*)&W[k * O + c0 + c];
    }
    for (int i = tid * 4; i < ROWS * K; i += 256 * 4) {
        int r = i / K, c = i % K;
        float4 v = make_float4(0.f, 0.f, 0.f, 0.f);
        if (row0 + r < n) v = *(const float4*)&X[(size_t)(row0 + r) * K + c];
        *(float4*)&Xs[i] = v;
    }
    __syncthreads();

    int warp = tid >> 5, lane = tid & 31;
    int cg = lane % LPG, rg = lane / LPG;
    int j = cg * 4;
    int rbase = (warp * RG + rg) * R;
    const float* xb = &Xs[rbase * K];

    double acc[R][2];
#pragma unroll
    for (int r = 0; r < R; r++) { acc[r][0] = 0.0; acc[r][1] = 0.0; }

#pragma unroll 2
    for (int k0 = 0; k0 < K; k0 += 4) {
        float4 xq[R];
#pragma unroll
        for (int r = 0; r < R; r++) xq[r] = *(const float4*)&xb[r * K + k0];
#pragma unroll
        for (int kk = 0; kk < 4; kk++) {
            double2 w = *(const double2*)&Ws[(k0 + kk) * OB + j];
#pragma unroll
            for (int r = 0; r < R; r++) {
                float xv = (kk == 0) ? xq[r].x : (kk == 1) ? xq[r].y
                         : (kk == 2) ? xq[r].z : xq[r].w;
                double xx = dup2(xv);
                ffma2(acc[r][0], w.x, xx);
                ffma2(acc[r][1], w.y, xx);
            }
        }
    }

#pragma unroll
    for (int r = 0; r < R; r++) {
        int row = row0 + rbase + r;
        if (row < n) {
            Half4 h;
            h.a = __float22half2_rn(make_float2(lo32(acc[r][0]), hi32(acc[r][0])));
            h.b = __float22half2_rn(make_float2(lo32(acc[r][1]), hi32(acc[r][1])));
            *(Half4*)&out[(size_t)row * O + c0 + j] = h;
        }
    }
}

// ---------------- CSR gather (fp16 in, fp32 acc/out) + self + bias + relu ----
template <int F>
__global__ void gather_kernel(const float* __restrict__ bias, float* __restrict__ O, int n) {
    constexpr int G = F / 8;   // 8 features per lane (16B half loads)
    int t = blockIdx.x * blockDim.x + threadIdx.x;
    int v = t / G;
    int q = t % G;
    if (v >= n) return;
    const __half* T = g_bufT;
    size_t fo = (size_t)q * 8;

    float acc[8];
    {
        float sw = g_selfw[v];
        uint4 r = *(const uint4*)&T[(size_t)v * F + fo];
        const __half2* h = (const __half2*)&r;
#pragma unroll
        for (int p = 0; p < 4; p++) {
            float2 f = __half22float2(h[p]);
            acc[2 * p] = sw * f.x;
            acc[2 * p + 1] = sw * f.y;
        }
    }

    int beg = g_off[v];
    int cnt = g_cnt[v];
#pragma unroll 4
    for (int i = 0; i < cnt; i++) {
        Edge e = g_csr[beg + i];
        uint4 r = *(const uint4*)&T[(size_t)e.s * F + fo];
        const __half2* h = (const __half2*)&r;
#pragma unroll
        for (int p = 0; p < 4; p++) {
            float2 f = __half22float2(h[p]);
            acc[2 * p] += e.w * f.x;
            acc[2 * p + 1] += e.w * f.y;
        }
    }

    float4 b0 = *(const float4*)&bias[fo];
    float4 b1 = *(const float4*)&bias[fo + 4];
    float* o = &O[(size_t)v * F + fo];
    float4 o0 = make_float4(fmaxf(acc[0] + b0.x, 0.f), fmaxf(acc[1] + b0.y, 0.f),
                            fmaxf(acc[2] + b0.z, 0.f), fmaxf(acc[3] + b0.w, 0.f));
    float4 o1 = make_float4(fmaxf(acc[4] + b1.x, 0.f), fmaxf(acc[5] + b1.y, 0.f),
                            fmaxf(acc[6] + b1.z, 0.f), fmaxf(acc[7] + b1.w, 0.f));
    *(float4*)&o[0] = o0;
    *(float4*)&o[4] = o1;
}

// ---------------- layer-3 gather fused with logistic head ----------------
__global__ void gather_head_kernel(const float* __restrict__ bias,
                                   const float* __restrict__ Wl,
                                   const float* __restrict__ bl,
                                   float* __restrict__ out, int n) {
    constexpr int F = 32, G = 4;
    int t = blockIdx.x * blockDim.x + threadIdx.x;
    int v = t / G;
    int q = t % G;
    if (v >= n) return;
    const __half* T = g_bufT;
    size_t fo = (size_t)q * 8;

    float acc[8];
    {
        float sw = g_selfw[v];
        uint4 r = *(const uint4*)&T[(size_t)v * F + fo];
        const __half2* h = (const __half2*)&r;
#pragma unroll
        for (int p = 0; p < 4; p++) {
            float2 f = __half22float2(h[p]);
            acc[2 * p] = sw * f.x;
            acc[2 * p + 1] = sw * f.y;
        }
    }

    int beg = g_off[v];
    int cnt = g_cnt[v];
#pragma unroll 4
    for (int i = 0; i < cnt; i++) {
        Edge e = g_csr[beg + i];
        uint4 r = *(const uint4*)&T[(size_t)e.s * F + fo];
        const __half2* h = (const __half2*)&r;
#pragma unroll
        for (int p = 0; p < 4; p++) {
            float2 f = __half22float2(h[p]);
            acc[2 * p] += e.w * f.x;
            acc[2 * p + 1] += e.w * f.y;
        }
    }

    float4 b0 = *(const float4*)&bias[fo];
    float4 b1 = *(const float4*)&bias[fo + 4];
    float4 w0 = *(const float4*)&Wl[fo];
    float4 w1 = *(const float4*)&Wl[fo + 4];
    float p = fmaxf(acc[0] + b0.x, 0.f) * w0.x + fmaxf(acc[1] + b0.y, 0.f) * w0.y +
              fmaxf(acc[2] + b0.z, 0.f) * w0.z + fmaxf(acc[3] + b0.w, 0.f) * w0.w +
              fmaxf(acc[4] + b1.x, 0.f) * w1.x + fmaxf(acc[5] + b1.y, 0.f) * w1.y +
              fmaxf(acc[6] + b1.z, 0.f) * w1.z + fmaxf(acc[7] + b1.w, 0.f) * w1.w;
#pragma unroll
    for (int off = 2; off; off >>= 1) p += __shfl_down_sync(0xffffffffu, p, off, G);
    if (q == 0) out[v] = 1.f / (1.f + __expf(-(p + bl[0])));
}

extern "C" void kernel_launch(void* const* d_in, const int* in_sizes, int n_in,
                              void* d_out, int out_size) {
    const float* x = (const float*)d_in[0];
    const void* ei = (const void*)d_in[1];
    const float* W1 = (const float*)d_in[2];
    const float* b1 = (const float*)d_in[3];
    const float* W2 = (const float*)d_in[4];
    const float* b2 = (const float*)d_in[5];
    const float* W3 = (const float*)d_in[6];
    const float* b3 = (const float*)d_in[7];
    const float* Wl = (const float*)d_in[8];
    const float* bl = (const float*)d_in[9];
    float* out = (float*)d_out;
    int n = NN;

    cudaFuncSetAttribute(gemm3_kernel<128, 128, 64>, cudaFuncAttributeMaxDynamicSharedMemorySize, 65536);
    cudaFuncSetAttribute(gemm3_kernel<128, 64, 64>, cudaFuncAttributeMaxDynamicSharedMemorySize, 65536);
    cudaFuncSetAttribute(gemm3_kernel<64, 32, 32>, cudaFuncAttributeMaxDynamicSharedMemorySize, 40960);

    __half* T;
    float* O;
    cudaGetSymbolAddress((void**)&T, g_bufT);
    cudaGetSymbolAddress((void**)&O, g_bufO);

    // preprocessing (gemm1 kept at the ncu-profiled local slot)
    k_pre0<<<(NN + 255) / 256, 256>>>(ei);
    k_count_deg<<<(EE + 255) / 256, 256>>>(ei);
    k_dinv<<<(NN + 255) / 256, 256>>>();

    // --- layer 1 GEMM: 128 -> 128, two 64-col slices, 64 rows/block ---
    gemm3_kernel<128, 128, 64><<<dim3((n + 63) / 64, 2), 256, 65536>>>(x, W1, T, n);

    // CSR build
    k_scan_local<<<NB, SCAN_B>>>();
    k_scan_bsum<<<1, 32>>>();
    k_scan_add<<<(NN + 255) / 256, 256>>>();
    k_build_csr<<<(EE + 255) / 256, 256>>>(ei);

    // --- layer 1 gather (G=16 lanes/node) ---
    gather_kernel<128><<<(n * 16 + 255) / 256, 256>>>(b1, O, n);

    // --- layer 2: 128 -> 64 ---
    gemm3_kernel<128, 64, 64><<<dim3((n + 63) / 64, 1), 256, 65536>>>(O, W2, T, n);
    gather_kernel<64><<<(n * 8 + 255) / 256, 256>>>(b2, O, n);

    // --- layer 3: 64 -> 32 + head ---
    gemm3_kernel<64, 32, 32><<<dim3((n + 127) / 128, 1), 256, 40960>>>(O, W3, T, n);
    gather_head_kernel<<<(n * 4 + 255) / 256, 256>>>(b3, Wl, bl, out, n);
}

// round 7
// speedup vs baseline: 1.9922x; 1.4726x over previous
#include <cuda_runtime.h>
#include <cuda_fp16.h>
#include <mma.h>
#include <math.h>

using namespace nvcuda;

#define NN 100000
#define EE 1600000
#define SCAN_B 512
#define NB ((NN + SCAN_B - 1) / SCAN_B)

struct __align__(8) Edge { int s; float w; };

// ---------------- scratch (alloc-free: __device__ globals) ----------------
__device__ int    g_is64;
__device__ int    g_deg[NN];
__device__ int    g_cnt[NN];
__device__ int    g_off[NN];
__device__ int    g_cur[NN];
__device__ int    g_bsum[NB];
__device__ int    g_bpre[NB];
__device__ float  g_dinv[NN];
__device__ float  g_selfw[NN];
__device__ Edge   g_csr[EE];
__device__ __half g_bufT[(size_t)NN * 128];   // transformed features (GEMM out), fp16
__device__ __half g_bufOh[(size_t)NN * 128];  // activations (gather out), fp16

// ---------------- detect dtype + init degrees ----------------
__global__ void k_pre0(const void* __restrict__ ei) {
    int i = blockIdx.x * blockDim.x + threadIdx.x;
    if (i < NN) g_deg[i] = 1;  // self-loop
    if (i == 0) {
        const int* w = (const int*)ei;
        int nz = 0;
        for (int k = 1; k < 256; k += 2) nz += (w[k] != 0);
        g_is64 = (nz == 0) ? 1 : 0;
    }
}

__device__ __forceinline__ int edge_at(const void* __restrict__ ei, long long i) {
    if (g_is64) return (int)((const long long*)ei)[i];
    return ((const int*)ei)[i];
}

__global__ void k_count_deg(const void* __restrict__ ei) {
    int i = blockIdx.x * blockDim.x + threadIdx.x;
    if (i < EE) atomicAdd(&g_deg[edge_at(ei, (long long)EE + i)], 1);
}

__global__ void k_dinv() {
    int i = blockIdx.x * blockDim.x + threadIdx.x;
    if (i < NN) {
        int dg = g_deg[i];
        float dv = rsqrtf((float)dg);
        g_dinv[i] = dv;
        g_selfw[i] = dv * dv;
        g_cnt[i] = dg - 1;
    }
}

// ---------------- CSR build ----------------
__global__ void k_scan_local() {
    __shared__ int sm[SCAN_B];
    int v = blockIdx.x * SCAN_B + threadIdx.x;
    int x = (v < NN) ? g_cnt[v] : 0;
    sm[threadIdx.x] = x;
    __syncthreads();
    for (int off = 1; off < SCAN_B; off <<= 1) {
        int y = (threadIdx.x >= off) ? sm[threadIdx.x - off] : 0;
        __syncthreads();
        sm[threadIdx.x] += y;
        __syncthreads();
    }
    if (v < NN) g_off[v] = sm[threadIdx.x] - x;
    if (threadIdx.x == SCAN_B - 1) g_bsum[blockIdx.x] = sm[SCAN_B - 1];
}

__global__ void k_scan_bsum() {
    if (threadIdx.x == 0 && blockIdx.x == 0) {
        int run = 0;
        for (int i = 0; i < NB; i++) { g_bpre[i] = run; run += g_bsum[i]; }
    }
}

__global__ void k_scan_add() {
    int v = blockIdx.x * blockDim.x + threadIdx.x;
    if (v < NN) {
        g_off[v] += g_bpre[v / SCAN_B];
        g_cur[v] = 0;
    }
}

__global__ void k_build_csr(const void* __restrict__ ei) {
    int e = blockIdx.x * blockDim.x + threadIdx.x;
    if (e >= EE) return;
    int s = edge_at(ei, e);
    int d = edge_at(ei, (long long)EE + e);
    Edge ed;
    ed.s = s;
    ed.w = g_dinv[s] * g_dinv[d];
    int pos = g_off[d] + atomicAdd(&g_cur[d], 1);
    g_csr[pos] = ed;
}

// ---------------- tensor-core GEMM: out[n,O] = half(X[n,K] @ W[K,O]) --------
// Block: 128 rows x O cols, single K shot in smem. 8 warps; warp w = 16-row
// strip, all O/16 n-tiles, fp32 accumulate. Output staged fp32 in smem
// (aliasing input tiles) then converted to fp16.
template <int K, int O, bool IN_HALF>
__global__ __launch_bounds__(256) void wgemm_kernel(const void* __restrict__ Xv,
                                                    const float* __restrict__ W,
                                                    __half* __restrict__ out, int n) {
    constexpr int LDA = K + 8;
    constexpr int LDB = O + 8;
    constexpr int NT = O / 16;
    extern __shared__ char smraw[];
    __half* Xs = (__half*)smraw;                     // 128 x LDA
    __half* Ws = ((__half*)smraw) + 128 * LDA;       // K x LDB
    float* Os = (float*)smraw;                       // 128 x O (aliases inputs)

    int tid = threadIdx.x;
    int warp = tid >> 5;
    int row0 = blockIdx.x * 128;

    // load X tile (convert fp32->fp16 if needed), zero-pad rows >= n
    for (int i = tid * 8; i < 128 * K; i += 256 * 8) {
        int r = i / K, c = i % K;
        uint4 pk = make_uint4(0u, 0u, 0u, 0u);
        if (row0 + r < n) {
            if constexpr (IN_HALF) {
                pk = *(const uint4*)&((const __half*)Xv)[(size_t)(row0 + r) * K + c];
            } else {
                const float* Xf = (const float*)Xv;
                float4 a = *(const float4*)&Xf[(size_t)(row0 + r) * K + c];
                float4 b = *(const float4*)&Xf[(size_t)(row0 + r) * K + c + 4];
                __half2* h = (__half2*)&pk;
                h[0] = __floats2half2_rn(a.x, a.y);
                h[1] = __floats2half2_rn(a.z, a.w);
                h[2] = __floats2half2_rn(b.x, b.y);
                h[3] = __floats2half2_rn(b.z, b.w);
            }
        }
        *(uint4*)&Xs[r * LDA + c] = pk;
    }
    // load W tile fp32 -> fp16
    for (int i = tid * 4; i < K * O; i += 256 * 4) {
        int k = i / O, c = i % O;
        float4 wv = *(const float4*)&W[(size_t)k * O + c];
        uint2 pk;
        ((__half2*)&pk)[0] = __floats2half2_rn(wv.x, wv.y);
        ((__half2*)&pk)[1] = __floats2half2_rn(wv.z, wv.w);
        *(uint2*)&Ws[k * LDB + c] = pk;
    }
    __syncthreads();

    wmma::fragment<wmma::accumulator, 16, 16, 16, float> acc[NT];
#pragma unroll
    for (int t = 0; t < NT; t++) wmma::fill_fragment(acc[t], 0.0f);

#pragma unroll
    for (int k0 = 0; k0 < K; k0 += 16) {
        wmma::fragment<wmma::matrix_a, 16, 16, 16, __half, wmma::row_major> a;
        wmma::load_matrix_sync(a, &Xs[warp * 16 * LDA + k0], LDA);
#pragma unroll
        for (int t = 0; t < NT; t++) {
            wmma::fragment<wmma::matrix_b, 16, 16, 16, __half, wmma::row_major> b;
            wmma::load_matrix_sync(b, &Ws[k0 * LDB + t * 16], LDB);
            wmma::mma_sync(acc[t], a, b, acc[t]);
        }
    }

    __syncthreads();  // inputs fully consumed; safe to alias Os
#pragma unroll
    for (int t = 0; t < NT; t++)
        wmma::store_matrix_sync(&Os[warp * 16 * O + t * 16], acc[t], O, wmma::mem_row_major);
    __syncthreads();

    for (int i = tid * 4; i < 128 * O; i += 256 * 4) {
        int r = i / O, c = i % O;
        int row = row0 + r;
        if (row < n) {
            float4 a = *(float4*)&Os[i];
            uint2 pk;
            ((__half2*)&pk)[0] = __floats2half2_rn(a.x, a.y);
            ((__half2*)&pk)[1] = __floats2half2_rn(a.z, a.w);
            *(uint2*)&out[(size_t)row * O + c] = pk;
        }
    }
}

// ---------------- CSR gather (fp16 in, fp32 acc, fp16 out) ----------------
template <int F>
__global__ void gather_kernel(const float* __restrict__ bias, __half* __restrict__ O, int n) {
    constexpr int G = F / 8;   // 8 features per lane
    int t = blockIdx.x * blockDim.x + threadIdx.x;
    int v = t / G;
    int q = t % G;
    if (v >= n) return;
    const __half* T = g_bufT;
    size_t fo = (size_t)q * 8;

    float acc[8];
    {
        float sw = g_selfw[v];
        uint4 r = *(const uint4*)&T[(size_t)v * F + fo];
        const __half2* h = (const __half2*)&r;
#pragma unroll
        for (int p = 0; p < 4; p++) {
            float2 f = __half22float2(h[p]);
            acc[2 * p] = sw * f.x;
            acc[2 * p + 1] = sw * f.y;
        }
    }

    int beg = g_off[v];
    int cnt = g_cnt[v];
#pragma unroll 4
    for (int i = 0; i < cnt; i++) {
        Edge e = g_csr[beg + i];
        uint4 r = *(const uint4*)&T[(size_t)e.s * F + fo];
        const __half2* h = (const __half2*)&r;
#pragma unroll
        for (int p = 0; p < 4; p++) {
            float2 f = __half22float2(h[p]);
            acc[2 * p] += e.w * f.x;
            acc[2 * p + 1] += e.w * f.y;
        }
    }

    float4 b0 = *(const float4*)&bias[fo];
    float4 b1 = *(const float4*)&bias[fo + 4];
    uint4 pk;
    ((__half2*)&pk)[0] = __floats2half2_rn(fmaxf(acc[0] + b0.x, 0.f), fmaxf(acc[1] + b0.y, 0.f));
    ((__half2*)&pk)[1] = __floats2half2_rn(fmaxf(acc[2] + b0.z, 0.f), fmaxf(acc[3] + b0.w, 0.f));
    ((__half2*)&pk)[2] = __floats2half2_rn(fmaxf(acc[4] + b1.x, 0.f), fmaxf(acc[5] + b1.y, 0.f));
    ((__half2*)&pk)[3] = __floats2half2_rn(fmaxf(acc[6] + b1.z, 0.f), fmaxf(acc[7] + b1.w, 0.f));
    *(uint4*)&O[(size_t)v * F + fo] = pk;
}

// ---------------- layer-3 gather fused with logistic head ----------------
__global__ void gather_head_kernel(const float* __restrict__ bias,
                                   const float* __restrict__ Wl,
                                   const float* __restrict__ bl,
                                   float* __restrict__ out, int n) {
    constexpr int F = 32, G = 4;
    int t = blockIdx.x * blockDim.x + threadIdx.x;
    int v = t / G;
    int q = t % G;
    if (v >= n) return;
    const __half* T = g_bufT;
    size_t fo = (size_t)q * 8;

    float acc[8];
    {
        float sw = g_selfw[v];
        uint4 r = *(const uint4*)&T[(size_t)v * F + fo];
        const __half2* h = (const __half2*)&r;
#pragma unroll
        for (int p = 0; p < 4; p++) {
            float2 f = __half22float2(h[p]);
            acc[2 * p] = sw * f.x;
            acc[2 * p + 1] = sw * f.y;
        }
    }

    int beg = g_off[v];
    int cnt = g_cnt[v];
#pragma unroll 4
    for (int i = 0; i < cnt; i++) {
        Edge e = g_csr[beg + i];
        uint4 r = *(const uint4*)&T[(size_t)e.s * F + fo];
        const __half2* h = (const __half2*)&r;
#pragma unroll
        for (int p = 0; p < 4; p++) {
            float2 f = __half22float2(h[p]);
            acc[2 * p] += e.w * f.x;
            acc[2 * p + 1] += e.w * f.y;
        }
    }

    float4 b0 = *(const float4*)&bias[fo];
    float4 b1 = *(const float4*)&bias[fo + 4];
    float4 w0 = *(const float4*)&Wl[fo];
    float4 w1 = *(const float4*)&Wl[fo + 4];
    float p = fmaxf(acc[0] + b0.x, 0.f) * w0.x + fmaxf(acc[1] + b0.y, 0.f) * w0.y +
              fmaxf(acc[2] + b0.z, 0.f) * w0.z + fmaxf(acc[3] + b0.w, 0.f) * w0.w +
              fmaxf(acc[4] + b1.x, 0.f) * w1.x + fmaxf(acc[5] + b1.y, 0.f) * w1.y +
              fmaxf(acc[6] + b1.z, 0.f) * w1.z + fmaxf(acc[7] + b1.w, 0.f) * w1.w;
#pragma unroll
    for (int off = 2; off; off >>= 1) p += __shfl_down_sync(0xffffffffu, p, off, G);
    if (q == 0) out[v] = 1.f / (1.f + __expf(-(p + bl[0])));
}

extern "C" void kernel_launch(void* const* d_in, const int* in_sizes, int n_in,
                              void* d_out, int out_size) {
    const float* x = (const float*)d_in[0];
    const void* ei = (const void*)d_in[1];
    const float* W1 = (const float*)d_in[2];
    const float* b1 = (const float*)d_in[3];
    const float* W2 = (const float*)d_in[4];
    const float* b2 = (const float*)d_in[5];
    const float* W3 = (const float*)d_in[6];
    const float* b3 = (const float*)d_in[7];
    const float* Wl = (const float*)d_in[8];
    const float* bl = (const float*)d_in[9];
    float* out = (float*)d_out;
    int n = NN;

    // smem: max(input tiles, fp32 output stage)
    constexpr int SM1 = (128 * (128 + 8) + 128 * (128 + 8)) * 2;  // 69632
    constexpr int SM2 = (128 * (128 + 8) + 128 * (64 + 8)) * 2;   // 53248
    constexpr int SM3 = (128 * (64 + 8) + 64 * (32 + 8)) * 2;     // 23552
    cudaFuncSetAttribute(wgemm_kernel<128, 128, false>, cudaFuncAttributeMaxDynamicSharedMemorySize, SM1);
    cudaFuncSetAttribute(wgemm_kernel<128, 64, true>, cudaFuncAttributeMaxDynamicSharedMemorySize, SM2);
    cudaFuncSetAttribute(wgemm_kernel<64, 32, true>, cudaFuncAttributeMaxDynamicSharedMemorySize, SM3);

    __half* T;
    __half* Oh;
    cudaGetSymbolAddress((void**)&T, g_bufT);
    cudaGetSymbolAddress((void**)&Oh, g_bufOh);

    // preprocessing (gemm1 kept at the ncu-profiled local slot)
    k_pre0<<<(NN + 255) / 256, 256>>>(ei);
    k_count_deg<<<(EE + 255) / 256, 256>>>(ei);
    k_dinv<<<(NN + 255) / 256, 256>>>();

    // --- layer 1 GEMM: 128 -> 128 (tensor cores) ---
    wgemm_kernel<128, 128, false><<<(n + 127) / 128, 256, SM1>>>(x, W1, T, n);

    // CSR build
    k_scan_local<<<NB, SCAN_B>>>();
    k_scan_bsum<<<1, 32>>>();
    k_scan_add<<<(NN + 255) / 256, 256>>>();
    k_build_csr<<<(EE + 255) / 256, 256>>>(ei);

    // --- layer 1 gather ---
    gather_kernel<128><<<(n * 16 + 255) / 256, 256>>>(b1, Oh, n);

    // --- layer 2: 128 -> 64 ---
    wgemm_kernel<128, 64, true><<<(n + 127) / 128, 256, SM2>>>(Oh, W2, T, n);
    gather_kernel<64><<<(n * 8 + 255) / 256, 256>>>(b2, Oh, n);

    // --- layer 3: 64 -> 32 + head ---
    wgemm_kernel<64, 32, true><<<(n + 127) / 128, 256, SM3>>>(Oh, W3, T, n);
    gather_head_kernel<<<(n * 4 + 255) / 256, 256>>>(b3, Wl, bl, out, n);
}